// round 9
// baseline (speedup 1.0000x reference)
#include <cuda_runtime.h>

#define DDIM  64
#define TLEN  256
#define HID   100
#define G3    300
#define NBLK  128
#define RPB   4
#define NT    960
#define STC   65
#define SROW  (STC*RPB)   // 260
#define HROW  (HID*RPB)   // 400
#define GROW  (G3*RPB)    // 1200

typedef unsigned long long u64;

__device__ __align__(16) float g_states[NBLK * TLEN * SROW];
__device__ __align__(16) float g_hback [NBLK * (TLEN + 1) * HROW];
__device__ __align__(16) float g_gi    [(size_t)NBLK * TLEN * GROW];

struct __align__(16) Smem {
    float sU [HID * G3];    // bgru_U (120000 B)
    float sWb[STC * G3];    // bgru_W ( 78000 B)
    float stGI[2 * GROW];   // gi partials, 2 slots ( 9600 B)
    float stGH[3 * GROW];   // gh partials, 3 slots (14400 B) [contiguous after stGI]
    float hsF[HROW];
    float hsB[HROW];
    float dec4[50 * RPB];
    float bF[2 * G3];
    float bB[2 * G3];
    int   obs[TLEN];
};  // 231824 B <= 232448 B limit

__device__ __forceinline__ float tanha(float x) {
    float y; asm("tanh.approx.f32 %0, %1;" : "=f"(y) : "f"(x)); return y;
}
__device__ __forceinline__ u64 pk2(float w) {
    unsigned wi = __float_as_uint(w);
    u64 r; asm("mov.b64 %0, {%1, %1};" : "=l"(r) : "r"(wi), "r"(wi)); return r;
}
__device__ __forceinline__ void fma2(u64& a, u64 v, u64 w) {
    asm("fma.rn.f32x2 %0, %1, %2, %0;" : "+l"(a) : "l"(v), "l"(w));
}

// matvec chunk, weights via generic/smem pointer (column base Wcol = W + j)
__device__ __forceinline__ void mv_sm(const float* __restrict__ Wcol, const float* hv_,
                                      int kb, int kn, u64& a01, u64& a23)
{
    const ulonglong2* hv = reinterpret_cast<const ulonglong2*>(hv_) + kb;
    const float* Wc = Wcol + kb * G3;
#pragma unroll 5
    for (int k = 0; k < kn; k++) {
        u64 w2 = pk2(Wc[k * G3]);
        ulonglong2 h = hv[k];
        fma2(a01, h.x, w2); fma2(a23, h.y, w2);
    }
}
// matvec chunk, weights via __ldg (global, L2-hot)
__device__ __forceinline__ void mv_gl(const float* __restrict__ Wcol, const float* hv_,
                                      int kb, int kn, u64& a01, u64& a23)
{
    const ulonglong2* hv = reinterpret_cast<const ulonglong2*>(hv_) + kb;
    const float* Wc = Wcol + kb * G3;
#pragma unroll 5
    for (int k = 0; k < kn; k++) {
        u64 w2 = pk2(__ldg(Wc + k * G3));
        ulonglong2 h = hv[k];
        fma2(a01, h.x, w2); fma2(a23, h.y, w2);
    }
}

// gates: combine partial slots, nonlinearity, update h (and optional h_back dict)
// giMode: 0 = combine 2 stGI slots, 1 = bias-only, 2 = prefetched pg registers
__device__ __forceinline__ void gates_apply(Smem* sm, int giMode, int nGH,
                                            const float* bias, const float* hsrc,
                                            float* hout, float* gdict, int tid,
                                            float pgz, float pgr, float pgn)
{
    if (tid < HROW) {
        int idx = tid;
        float giz, gir, gin;
        if (giMode == 0) {
            giz = sm->stGI[idx]            + sm->stGI[GROW + idx];
            gir = sm->stGI[HROW + idx]     + sm->stGI[GROW + HROW + idx];
            gin = sm->stGI[2 * HROW + idx] + sm->stGI[GROW + 2 * HROW + idx];
        } else if (giMode == 1) {
            int i = idx >> 2;
            giz = bias[i]; gir = bias[HID + i]; gin = bias[2 * HID + i];
        } else { giz = pgz; gir = pgr; gin = pgn; }
        float ghz = sm->stGH[idx]            + sm->stGH[GROW + idx];
        float ghr = sm->stGH[HROW + idx]     + sm->stGH[GROW + HROW + idx];
        float ghn = sm->stGH[2 * HROW + idx] + sm->stGH[GROW + 2 * HROW + idx];
        if (nGH == 3) {
            ghz += sm->stGH[2 * GROW + idx];
            ghr += sm->stGH[2 * GROW + HROW + idx];
            ghn += sm->stGH[2 * GROW + 2 * HROW + idx];
        }
        float z  = fmaf(0.5f, tanha(0.5f * (giz + ghz)), 0.5f);
        float rr = fmaf(0.5f, tanha(0.5f * (gir + ghr)), 0.5f);
        float n  = tanha(fmaf(rr, ghn, gin));
        float hnew = fmaf(z, hsrc[idx] - n, n);
        hout[idx] = hnew;
        if (gdict) gdict[idx] = hnew;
    }
    __syncthreads();
}

// ---- sweep step: gi precomputed; gh 3-way split 34/33/33 ----
__device__ __forceinline__ void sweep_step(Smem* sm, const float* __restrict__ gv,
                                           float* gdict, int tid, int third, int j)
{
    float pgz = 0.f, pgr = 0.f, pgn = 0.f;
    if (tid < HROW) {
        pgz = __ldg(gv + tid); pgr = __ldg(gv + HROW + tid); pgn = __ldg(gv + 2 * HROW + tid);
    }
    if (tid < 900) {
        int kb = (third == 0) ? 0 : ((third == 1) ? 34 : 67);
        int kn = (third == 0) ? 34 : 33;
        u64 a01 = (third == 0) ? pk2(sm->bB[G3 + j]) : 0ull, a23 = a01;
        mv_sm(sm->sU + j, sm->hsB, kb, kn, a01, a23);
        reinterpret_cast<ulonglong2*>(sm->stGH)[third * G3 + j] = make_ulonglong2(a01, a23);
    }
    __syncthreads();
    gates_apply(sm, 2, 3, sm->bB, sm->hsB, sm->hsB, gdict, tid, pgz, pgr, pgn);
}

// ---- backward GRU step (recompute path): balanced 55/55/55 split ----
template<bool HASX>
__device__ __forceinline__ void back_step(Smem* sm, const float* xg, const float* hsrc,
                                          float* gdict, int tid, int third, int j)
{
    if (tid < 900) {
        if (third < 2) {
            int kb = third ? 55 : 0, kn = third ? 45 : 55;
            u64 a01 = third ? 0ull : pk2(sm->bB[G3 + j]), a23 = a01;
            mv_sm(sm->sU + j, hsrc, kb, kn, a01, a23);
            reinterpret_cast<ulonglong2*>(sm->stGH)[third * G3 + j] = make_ulonglong2(a01, a23);
        }
        if (HASX && third >= 1) {
            int kb = (third == 1) ? 0 : 10, kn = (third == 1) ? 10 : 55;
            u64 a01 = (third == 1) ? pk2(sm->bB[j]) : 0ull, a23 = a01;
            mv_sm(sm->sWb + j, xg, kb, kn, a01, a23);
            reinterpret_cast<ulonglong2*>(sm->stGI)[(third - 1) * G3 + j] = make_ulonglong2(a01, a23);
        }
    }
    __syncthreads();
    gates_apply(sm, HASX ? 0 : 1, 2, sm->bB, hsrc, sm->hsB, gdict, tid, 0.f, 0.f, 0.f);
}

// ---- forward GRU step: balanced 55/55/54 split, weights via __ldg ----
__device__ __forceinline__ void fwd_step(const float* __restrict__ gruU,
                                         const float* __restrict__ gruW,
                                         Smem* sm, const float* xg, int tid, int third, int j)
{
    if (tid < 900) {
        if (third < 2) {
            int kb = third ? 55 : 0, kn = third ? 45 : 55;
            u64 a01 = third ? 0ull : pk2(sm->bF[G3 + j]), a23 = a01;
            mv_gl(gruU + j, sm->hsF, kb, kn, a01, a23);
            reinterpret_cast<ulonglong2*>(sm->stGH)[third * G3 + j] = make_ulonglong2(a01, a23);
        }
        if (third >= 1) {
            int kb = (third == 1) ? 0 : 10, kn = (third == 1) ? 10 : 54;
            u64 a01 = (third == 1) ? pk2(sm->bF[j]) : 0ull, a23 = a01;
            // x channels 1..64 of the state row
            const ulonglong2* hv = reinterpret_cast<const ulonglong2*>(xg) + 1 + kb;
            const float* Wc = gruW + kb * G3 + j;
#pragma unroll 5
            for (int k = 0; k < kn; k++) {
                u64 w2 = pk2(__ldg(Wc + k * G3));
                ulonglong2 x = hv[k];
                fma2(a01, x.x, w2); fma2(a23, x.y, w2);
            }
            reinterpret_cast<ulonglong2*>(sm->stGI)[(third - 1) * G3 + j] = make_ulonglong2(a01, a23);
        }
    }
    __syncthreads();
    gates_apply(sm, 0, 2, sm->bF, sm->hsF, sm->hsF, nullptr, tid, 0.f, 0.f, 0.f);
}

// ---- decoder event ----
__device__ __forceinline__ void decoder_event(int lvl,
                                              const float* __restrict__ decW,
                                              const float* __restrict__ decB,
                                              const float* __restrict__ meanW,
                                              const float* __restrict__ meanB,
                                              Smem* sm, const float* hbg,
                                              float* gout, int tid)
{
    float* stage = sm->stGI;          // stGI+stGH contiguous scratch (24000 B)
    if (tid < 500) {                  // [4,200]@[200,50], k in 10 groups of 20
        int j = tid % 50, kg = tid / 50;
        u64 a01 = 0, a23 = 0;
        const float* Wl = decW + lvl * 200 * 50;
        int kbeg = kg * 20;
#pragma unroll 5
        for (int kk = 0; kk < 20; kk++) {
            int k = kbeg + kk;
            const float* src = (k < HID) ? (sm->hsF + k * RPB) : (hbg + (k - HID) * RPB);
            ulonglong2 h = *reinterpret_cast<const ulonglong2*>(src);
            u64 w2 = pk2(__ldg(&Wl[k * 50 + j]));
            fma2(a01, h.x, w2); fma2(a23, h.y, w2);
        }
        reinterpret_cast<ulonglong2*>(stage)[tid] = make_ulonglong2(a01, a23);
    }
    __syncthreads();
    if (tid < 50) {
        float b = __ldg(&decB[lvl * 50 + tid]);
        float s0 = b, s1 = b, s2 = b, s3 = b;
#pragma unroll
        for (int g = 0; g < 10; g++) {
            int base = (g * 50 + tid) * 4;
            s0 += stage[base]; s1 += stage[base + 1]; s2 += stage[base + 2]; s3 += stage[base + 3];
        }
        sm->dec4[tid * 4 + 0] = fmaxf(s0, 0.f); sm->dec4[tid * 4 + 1] = fmaxf(s1, 0.f);
        sm->dec4[tid * 4 + 2] = fmaxf(s2, 0.f); sm->dec4[tid * 4 + 3] = fmaxf(s3, 0.f);
    }
    __syncthreads();
    if (tid < 640) {                  // [4,50]@[50,64], k in 10 groups of 5
        int j = tid & 63, kg = tid >> 6;
        u64 m01 = 0, m23 = 0;
        const float* Ml = meanW + lvl * 50 * DDIM;
        int kbeg = kg * 5;
#pragma unroll
        for (int kk = 0; kk < 5; kk++) {
            int k = kbeg + kk;
            ulonglong2 d = reinterpret_cast<const ulonglong2*>(sm->dec4)[k];
            u64 w2 = pk2(__ldg(&Ml[k * DDIM + j]));
            fma2(m01, d.x, w2); fma2(m23, d.y, w2);
        }
        reinterpret_cast<ulonglong2*>(stage)[tid] = make_ulonglong2(m01, m23);
    }
    __syncthreads();
    if (tid < DDIM) {
        float b = __ldg(&meanB[lvl * DDIM + tid]);
        float s0 = b, s1 = b, s2 = b, s3 = b;
#pragma unroll
        for (int g = 0; g < 10; g++) {
            int base = (g * DDIM + tid) * 4;
            s0 += stage[base]; s1 += stage[base + 1]; s2 += stage[base + 2]; s3 += stage[base + 3];
        }
        gout[tid * RPB + 0] = s0; gout[tid * RPB + 1] = s1;
        gout[tid * RPB + 2] = s2; gout[tid * RPB + 3] = s3;
    }
    if (tid >= DDIM && tid < DDIM + RPB) gout[DDIM * RPB + (tid - DDIM)] = 1.0f;
    __syncthreads();
}

__global__ void __launch_bounds__(NT, 1)
naomi_kernel(const float* __restrict__ a,
             const float* __restrict__ gruW,  const float* __restrict__ gruU,
             const float* __restrict__ gruB,
             const float* __restrict__ bgruW, const float* __restrict__ bgruU,
             const float* __restrict__ bgruB,
             const float* __restrict__ decW,  const float* __restrict__ decB,
             const float* __restrict__ meanW, const float* __restrict__ meanB,
             float* __restrict__ out)
{
    extern __shared__ __align__(16) char smraw[];
    Smem* sm = reinterpret_cast<Smem*>(smraw);
    const int tid = threadIdx.x;
    const int bid = blockIdx.x;
    const int third = (tid < 900) ? (tid / 300) : 0;
    const int j     = (tid < 900) ? (tid - third * 300) : 0;

    for (int i = tid; i < HID * G3; i += NT) sm->sU[i]  = bgruU[i];
    for (int i = tid; i < STC * G3; i += NT) sm->sWb[i] = bgruW[i];
    for (int i = tid; i < 2 * G3;   i += NT) { sm->bF[i] = gruB[i]; sm->bB[i] = bgruB[i]; }

    for (int t = tid; t < TLEN; t += NT) sm->obs[t] = (a[t * 3 + 2] > 0.5f) ? 1 : 0;

    float* gst = g_states + bid * TLEN * SROW;
    float* ghb = g_hback  + bid * (TLEN + 1) * HROW;
    float* ggi = g_gi     + (size_t)bid * TLEN * GROW;
    const int b0row = bid * RPB;
    for (int idx = tid; idx < RPB * STC * TLEN; idx += NT) {
        int t = idx & (TLEN - 1);
        int tmp = idx >> 8;
        int k = tmp % STC, r = tmp / STC;
        int b = b0row + r;
        float v = (k < DDIM) ? a[((b * DDIM + k) * TLEN + t) * 3]
                             : a[((b * DDIM) * TLEN + t) * 3 + 2];
        gst[t * SROW + k * RPB + r] = v;
    }
    for (int i = tid; i < HROW; i += NT) {
        sm->hsB[i] = 0.f; sm->hsF[i] = 0.f; ghb[TLEN * HROW + i] = 0.f;
    }
    __syncthreads();

    // ---- parallel prepass: gi[t] = states[t] @ bgru_W + b0, t = 1..255 ----
    for (int task = tid; task < (TLEN - 1) * G3; task += NT) {
        int t = task / G3 + 1;
        int jj = task - (t - 1) * G3;
        u64 a01 = pk2(sm->bB[jj]), a23 = a01;
        const ulonglong2* xv = reinterpret_cast<const ulonglong2*>(gst + t * SROW);
#pragma unroll 5
        for (int k = 0; k < STC; k++) {
            u64 w2 = pk2(sm->sWb[k * G3 + jj]);
            ulonglong2 x = xv[k];
            fma2(a01, x.x, w2); fma2(a23, x.y, w2);
        }
        reinterpret_cast<ulonglong2*>(ggi)[(size_t)t * G3 + jj] = make_ulonglong2(a01, a23);
    }
    __syncthreads();

    // ---- phase 1: backward sweep ----
    for (int t = TLEN - 1; t >= 1; t--)
        sweep_step(sm, ggi + (size_t)t * GROW, ghb + t * HROW, tid, third, j);

    // ---- phase 2: forward interpolation ----
    fwd_step(gruU, gruW, sm, gst, tid, third, j);

    int curr_p = 0;
    while (curr_p < TLEN - 1) {
        if (sm->obs[curr_p + 1]) {
            curr_p++;
            fwd_step(gruU, gruW, sm, gst + curr_p * SROW, tid, third, j);
        } else {
            int next_p = curr_p + 1;
            while (next_p < TLEN && !sm->obs[next_p]) next_p++;
            int step = 1;
            while (curr_p + 2 * step <= next_p && step <= 8) step <<= 1;
            if (step > 1) step >>= 1;
            int lvl = (step == 8) ? 3 : (step == 4) ? 2 : (step == 2) ? 1 : 0;

            decoder_event(lvl, decW, decB, meanW, meanB, sm,
                          ghb + (curr_p + 2 * step) * HROW,
                          gst + (curr_p + step) * SROW, tid);

            if (step > 1) {
                int right = curr_p + step, left = curr_p + (step >> 1);
                back_step<true>(sm, gst + right * SROW, ghb + (right + 1) * HROW,
                                ghb + right * HROW, tid, third, j);
                for (int i2 = right - 1; i2 >= left; i2--)
                    back_step<false>(sm, nullptr, sm->hsB, ghb + i2 * HROW, tid, third, j);
            }
            sm->obs[curr_p + step] = 1;
            __syncthreads();
        }
    }

    // ---- output: out[b][d][t] = states[t][b][d+1] ----
    __syncthreads();
    for (int idx = tid; idx < RPB * DDIM * TLEN; idx += NT) {
        int t = idx & (TLEN - 1);
        int tmp = idx >> 8;
        int d = tmp % DDIM, r = tmp / DDIM;
        int b = b0row + r;
        out[(b * DDIM + d) * TLEN + t] = gst[t * SROW + (d + 1) * RPB + r];
    }
}

extern "C" void kernel_launch(void* const* d_in, const int* in_sizes, int n_in,
                              void* d_out, int out_size)
{
    const float* a     = (const float*)d_in[0];
    const float* gruW  = (const float*)d_in[1];
    const float* gruU  = (const float*)d_in[2];
    const float* gruB  = (const float*)d_in[3];
    const float* bgruW = (const float*)d_in[4];
    const float* bgruU = (const float*)d_in[5];
    const float* bgruB = (const float*)d_in[6];
    const float* decW  = (const float*)d_in[7];
    const float* decB  = (const float*)d_in[8];
    const float* meanW = (const float*)d_in[9];
    const float* meanB = (const float*)d_in[10];
    float* out = (float*)d_out;

    static int smem_set = 0;
    if (!smem_set) {
        cudaFuncSetAttribute(naomi_kernel, cudaFuncAttributeMaxDynamicSharedMemorySize,
                             (int)sizeof(Smem));
        smem_set = 1;
    }
    naomi_kernel<<<NBLK, NT, sizeof(Smem)>>>(a, gruW, gruU, gruB, bgruW, bgruU, bgruB,
                                             decW, decB, meanW, meanB, out);
}